// round 10
// baseline (speedup 1.0000x reference)
#include <cuda_runtime.h>
#include <math.h>

#define FRAME_SIZE 160
#define LPC_N 16
#define T_LEN 2400
#define T4 (T_LEN / 4)              // 600 float4 per row
#define N_FRAMES 15
#define B_SZ 1024

#define GPW 30                      // float4 groups per warp (120 samples)
#define WARPS_PER_ROW (T4 / GPW)    // 20
#define WPB 4                       // warps per block
#define NTHREADS (WPB * 32)         // 128
#define BLOCKS_PER_ROW (WARPS_PER_ROW / WPB)  // 5

#define SCALE    (255.0f / 32768.0f)
#define SCALE_1  (32768.0f / 255.0f)

__device__ __forceinline__ float ex2_approx(float x) {
    float y; asm("ex2.approx.f32 %0, %1;" : "=f"(y) : "f"(x)); return y;
}
__device__ __forceinline__ float lg2_approx(float x) {
    float y; asm("lg2.approx.f32 %0, %1;" : "=f"(y) : "f"(x)); return y;
}

// mu-law (0..255) -> linear.  exp(u/128*ln256) == 2^(u/16).  u2l(128) == 0.
__device__ __forceinline__ float u2l(float v) {
    float u = v - 128.0f;
    float m = fmaf(SCALE_1, ex2_approx(fabsf(u) * 0.0625f), -SCALE_1);
    return copysignf(m, u);
}
// l2u(-a) = clip(128 - copysign(16*log2(1 + SCALE*|a|), a), 0, 255)
__device__ __forceinline__ float l2u_neg(float a) {
    float u = lg2_approx(fmaf(SCALE, fabsf(a), 1.0f));
    float s = copysignf(16.0f, a);
    return fminf(fmaxf(fmaf(-s, u, 128.0f), 0.0f), 255.0f);
}

__device__ __forceinline__ float4 dec4(float4 v) {
    float4 d;
    d.x = u2l(v.x); d.y = u2l(v.y); d.z = u2l(v.z); d.w = u2l(v.w);
    return d;
}

// Warp-autonomous: each warp owns 120 samples + decodes its own 16-sample
// halo (lanes 0-3). Per-warp smem strip, __syncwarp only — no cross-warp
// coupling, so a warp proceeds as soon as ITS loads land.
__global__ __launch_bounds__(NTHREADS)
void diff_pred_kernel(const float4* __restrict__ sig,
                      const float*  __restrict__ lpc,
                      float4* __restrict__ out) {
    __shared__ __align__(16) float4 sxw[WPB][4 + GPW];   // per-warp halo+data

    const int bx  = blockIdx.x;
    const int b   = bx / BLOCKS_PER_ROW;
    const int wid = threadIdx.x >> 5;
    const int l   = threadIdx.x & 31;
    const int wr  = (bx % BLOCKS_PER_ROW) * WPB + wid;   // warp-in-row 0..19
    const int gb  = wr * GPW;                            // group base in row
    const bool active = (l < GPW);
    const int g = gb + l;                                // this lane's group

    const float4* srow = sig + (size_t)b * T4;

    // ---- front-batch all global loads ----
    float4 v, c0, c1, c2, c3;
    if (active) {
        v = srow[g];
        const int f = g / (FRAME_SIZE / 4);              // frame = g/40
        const float4* lrow = (const float4*)(lpc + (size_t)b * (N_FRAMES * LPC_N)
                                             + f * LPC_N);
        c0 = lrow[0]; c1 = lrow[1]; c2 = lrow[2]; c3 = lrow[3];
    }
    if (l < 4) {
        // halo groups gb-4 .. gb-1; value 128 decodes to linear 0 (history pad)
        float4 h = (wr == 0) ? make_float4(128.f, 128.f, 128.f, 128.f)
                             : srow[gb - 4 + l];
        sxw[wid][l] = dec4(h);
    }
    if (active) sxw[wid][4 + l] = dec4(v);
    __syncwarp();

    if (!active) return;

    // 20-sample window sxw[wid][l .. l+4] (5 LDS.128)
    float x[20];
#pragma unroll
    for (int k = 0; k < 5; ++k) {
        float4 xx = sxw[wid][l + k];
        x[4 * k] = xx.x; x[4 * k + 1] = xx.y; x[4 * k + 2] = xx.z; x[4 * k + 3] = xx.w;
    }

    const float c[LPC_N] = { c0.x, c0.y, c0.z, c0.w, c1.x, c1.y, c1.z, c1.w,
                             c2.x, c2.y, c2.z, c2.w, c3.x, c3.y, c3.z, c3.w };

    // output sample 4*g + j uses x[16 + j - i], i = 0..15
    float a0 = 0.f, a1 = 0.f, a2 = 0.f, a3 = 0.f;
#pragma unroll
    for (int i = 0; i < LPC_N; ++i) {
        a0 = fmaf(c[i], x[16 - i], a0);
        a1 = fmaf(c[i], x[17 - i], a1);
        a2 = fmaf(c[i], x[18 - i], a2);
        a3 = fmaf(c[i], x[19 - i], a3);
    }

    float4 r;
    r.x = l2u_neg(a0); r.y = l2u_neg(a1); r.z = l2u_neg(a2); r.w = l2u_neg(a3);
    out[(size_t)b * T4 + g] = r;
}

extern "C" void kernel_launch(void* const* d_in, const int* in_sizes, int n_in,
                              void* d_out, int out_size) {
    const float4* sig = (const float4*)d_in[0];  // (B, 2400, 1) f32
    const float*  lpc = (const float*)d_in[1];   // (B, 15, 16) f32
    float4* out = (float4*)d_out;                // (B, 2400, 1) f32

    dim3 grid(B_SZ * BLOCKS_PER_ROW);            // 5120 blocks
    dim3 block(NTHREADS);
    diff_pred_kernel<<<grid, block>>>(sig, lpc, out);
}